// round 10
// baseline (speedup 1.0000x reference)
#include <cuda_runtime.h>
#include <cuda_bf16.h>
#include <cstdint>

// Select: sims GEMM on tensor cores (mma.sync bf16 hi/lo split, fp32 accum) +
// bidirectional sparsemax pooling.
// R10: one block = 1 image x 2 captions (M=64, N=128). A staging + A-ldmatrix
//      amortized over 2 pairs; 8192 blocks; sparsemax 1 thread/vector with all
//      256 threads busy (256 vectors = 2 pairs x (64 rows + 64 cols)).

#define KS 136        // padded bf16 row stride (272B rows)
#define TSTRIDE 131   // f32 tile stride: 3k mod 32 bijective -> conflict-free rows

// smem byte offsets (plane = 64 rows * KS bf16 = 17408 B)
#define SM_AH   0
#define SM_AL   17408
#define SM_B0H  34816
#define SM_B0L  52224
#define SM_B1H  69632
#define SM_B1L  87040
#define SM_DOT  104448         // rowdot[128] f32 (cap*64 + k)
#define SM_COL  104960         // coldot[128] f32 (cap*64 + l)
#define SM_RED  105472         // red[4] f32
#define SM_TOTAL 105488
#define SM_TILE 0              // f32 [64][131] aliased over AH/AL (dead after MMA)

// ---- precomputed bf16 hi/lo planes: per tensor-slice 1024 uint4 (16KB) ----
__device__ uint4 g_ih[131072];   // imgs hi  (2MB)
__device__ uint4 g_il[131072];   // imgs lo
__device__ uint4 g_ch[131072];   // caps hi
__device__ uint4 g_cl[131072];   // caps lo

static __device__ __forceinline__ uint32_t smem_u32(const void* p) {
    uint32_t a;
    asm("{ .reg .u64 t; cvta.to.shared.u64 t, %1; cvt.u32.u64 %0, t; }"
        : "=r"(a) : "l"(p));
    return a;
}

#define LDSM_X4(r0, r1, r2, r3, addr)                                          \
    asm volatile("ldmatrix.sync.aligned.m8n8.x4.shared.b16 {%0,%1,%2,%3}, [%4];" \
                 : "=r"(r0), "=r"(r1), "=r"(r2), "=r"(r3) : "r"(addr))

#define MMA16816(c, a, b0v, b1v)                                               \
    asm volatile("mma.sync.aligned.m16n8k16.row.col.f32.bf16.bf16.f32 "        \
                 "{%0,%1,%2,%3}, {%4,%5,%6,%7}, {%8,%9}, {%0,%1,%2,%3};"       \
                 : "+f"((c)[0]), "+f"((c)[1]), "+f"((c)[2]), "+f"((c)[3])      \
                 : "r"((a)[0]), "r"((a)[1]), "r"((a)[2]), "r"((a)[3]),         \
                   "r"(b0v), "r"(b1v))

static __device__ __forceinline__ void split4(float4 v, uint2& hi, uint2& lo) {
    __nv_bfloat16 h0 = __float2bfloat16(v.x), h1 = __float2bfloat16(v.y);
    __nv_bfloat16 h2 = __float2bfloat16(v.z), h3 = __float2bfloat16(v.w);
    __nv_bfloat16 l0 = __float2bfloat16(v.x - __bfloat162float(h0));
    __nv_bfloat16 l1 = __float2bfloat16(v.y - __bfloat162float(h1));
    __nv_bfloat16 l2 = __float2bfloat16(v.z - __bfloat162float(h2));
    __nv_bfloat16 l3 = __float2bfloat16(v.w - __bfloat162float(h3));
    hi.x = ((uint32_t)__bfloat16_as_ushort(h1) << 16) | __bfloat16_as_ushort(h0);
    hi.y = ((uint32_t)__bfloat16_as_ushort(h3) << 16) | __bfloat16_as_ushort(h2);
    lo.x = ((uint32_t)__bfloat16_as_ushort(l1) << 16) | __bfloat16_as_ushort(l0);
    lo.y = ((uint32_t)__bfloat16_as_ushort(l3) << 16) | __bfloat16_as_ushort(l2);
}

// ---- Prologue: fp32 -> bf16 hi/lo planes, once per launch ----
__global__ __launch_bounds__(256)
void split_kernel(const float4* __restrict__ imgs, const float4* __restrict__ caps)
{
    int idx = blockIdx.x * 256 + threadIdx.x;        // 0..262143
    const bool isimg = idx < 131072;
    int e = isimg ? idx : idx - 131072;
    const float4* src = isimg ? imgs : caps;
    uint4* hp = isimg ? g_ih : g_ch;
    uint4* lp = isimg ? g_il : g_cl;
    float4 v0 = src[2 * e], v1 = src[2 * e + 1];
    uint2 h0, l0, h1, l1;
    split4(v0, h0, l0);
    split4(v1, h1, l1);
    hp[e] = make_uint4(h0.x, h0.y, h1.x, h1.y);
    lp[e] = make_uint4(l0.x, l0.y, l1.x, l1.y);
}

__global__ __launch_bounds__(256, 2)
void select_mma_kernel(const int* __restrict__ img_lens,
                       const int* __restrict__ cap_lens,
                       float* __restrict__ out)
{
    extern __shared__ char smc[];
    const int tp = blockIdx.x;  // caption pair: t0=2tp, t1=2tp+1
    const int i = blockIdx.y;   // image
    const int tid = threadIdx.x;
    const int wid = tid >> 5, lane = tid & 31;
    const uint32_t sb = smem_u32(smc);

    const int ilen  = img_lens[i];
    const int tlen0 = cap_lens[2 * tp];
    const int tlen1 = cap_lens[2 * tp + 1];

    // ---- Stage A(image) + 2 B(caption) bf16 hi/lo planes via cp.async ----
    {
        const uint4* planes[6] = {
            g_ih + i * 1024,            g_il + i * 1024,
            g_ch + (2 * tp) * 1024,     g_cl + (2 * tp) * 1024,
            g_ch + (2 * tp + 1) * 1024, g_cl + (2 * tp + 1) * 1024 };
        const uint32_t doff[6] = { SM_AH, SM_AL, SM_B0H, SM_B0L, SM_B1H, SM_B1L };
#pragma unroll
        for (int p = 0; p < 6; ++p) {
            unsigned long long gb =
                (unsigned long long)__cvta_generic_to_global(planes[p]);
#pragma unroll
            for (int k = 0; k < 4; ++k) {
                int c = tid + k * 256;                 // 0..1023
                uint32_t row = (uint32_t)c >> 4, sub = (uint32_t)c & 15;
                uint32_t sa = sb + doff[p] + row * (KS * 2) + sub * 16;
                asm volatile("cp.async.cg.shared.global [%0], [%1], 16;"
                             :: "r"(sa), "l"(gb + (unsigned long long)c * 16)
                             : "memory");
            }
        }
        asm volatile("cp.async.commit_group;" ::: "memory");
        asm volatile("cp.async.wait_group 0;" ::: "memory");
    }
    __syncthreads();

    // ---- GEMM: 8 warps = 4(m) x 2(n-caption); warp tile 16x64; K=128 ----
    const int mw = wid & 3, nw = wid >> 2;
    const int mrow = mw * 16;

    const int arow = mrow + (lane & 15);
    const int acol = (lane >> 4) << 3;
    const uint32_t aoff = (uint32_t)(arow * KS + acol) * 2;
    const int brow = ((lane >> 4) << 3) + (lane & 7);
    const int bcol = ((lane >> 3) & 1) << 3;
    const uint32_t boff = (uint32_t)(brow * KS + bcol) * 2;
    const uint32_t bh_base = sb + (nw ? SM_B1H : SM_B0H) + boff;
    const uint32_t bl_base = sb + (nw ? SM_B1L : SM_B0L) + boff;

    float c[8][4];
#pragma unroll
    for (int j = 0; j < 8; j++)
#pragma unroll
        for (int r = 0; r < 4; r++) c[j][r] = 0.0f;

#pragma unroll
    for (int kk = 0; kk < 8; ++kk) {
        const uint32_t kb = (uint32_t)kk * 32;         // 16 bf16 = 32 B
        uint32_t ah[4], al[4], bh[16], bl[16];
        LDSM_X4(ah[0], ah[1], ah[2], ah[3], sb + SM_AH + aoff + kb);
        LDSM_X4(al[0], al[1], al[2], al[3], sb + SM_AL + aoff + kb);
#pragma unroll
        for (int g = 0; g < 4; ++g) {
            const uint32_t go = (uint32_t)g * 16 * KS * 2 + kb;
            LDSM_X4(bh[4 * g], bh[4 * g + 1], bh[4 * g + 2], bh[4 * g + 3], bh_base + go);
            LDSM_X4(bl[4 * g], bl[4 * g + 1], bl[4 * g + 2], bl[4 * g + 3], bl_base + go);
        }
#pragma unroll
        for (int j = 0; j < 8; ++j) {
            MMA16816(c[j], ah, bh[2 * j], bh[2 * j + 1]);   // Ah*Bh
            MMA16816(c[j], ah, bl[2 * j], bl[2 * j + 1]);   // Ah*Bl
            MMA16816(c[j], al, bh[2 * j], bh[2 * j + 1]);   // Al*Bh
        }
    }
    __syncthreads();   // A/B smem reads complete; tile alias safe

    // ---- Scatter masked fragments into f32 tile [64][131] ----
    {
        float* tile = (float*)(smc + SM_TILE);
        const int rowg = lane >> 2, colg = (lane & 3) * 2;
        const int tl = nw ? tlen1 : tlen0;
#pragma unroll
        for (int j = 0; j < 8; ++j) {
            const int l = j * 8 + colg;                // 0..63 within caption
            const int cl = nw * 64 + l;                // tile column
            const int r0 = mrow + rowg;
            const bool cm0 = l < tl, cm1 = (l + 1) < tl;
            tile[r0 * TSTRIDE + cl]           = (r0 < ilen && cm0) ? c[j][0] : -1.0f;
            tile[r0 * TSTRIDE + cl + 1]       = (r0 < ilen && cm1) ? c[j][1] : -1.0f;
            tile[(r0 + 8) * TSTRIDE + cl]     = ((r0 + 8) < ilen && cm0) ? c[j][2] : -1.0f;
            tile[(r0 + 8) * TSTRIDE + cl + 1] = ((r0 + 8) < ilen && cm1) ? c[j][3] : -1.0f;
        }
    }
    __syncthreads();

    // ---- Sparsemax (Michelot, exact): 1 thread per vector, 256 vectors ----
    // tid<128: row-vector (cap = tid>>6, k = tid&63): tile[k][cap*64 + 0..63]
    // tid>=128: col-vector (cap, l): tile[0..63][cap*64 + l]
    {
        const float* tile = (const float*)(smc + SM_TILE);
        float z[64];
        if (tid < 128) {
            const int cap = tid >> 6, k = tid & 63;
            const float* rp = tile + k * TSTRIDE + cap * 64;
#pragma unroll
            for (int j = 0; j < 64; j++) z[j] = rp[j];
        } else {
            const int idx = tid - 128, cap = idx >> 6, l = idx & 63;
            const float* cp = tile + cap * 64 + l;
#pragma unroll
            for (int j = 0; j < 64; j++) z[j] = cp[j * TSTRIDE];
        }

        float s0 = 0.f, s1 = 0.f, s2 = 0.f, s3 = 0.f;
#pragma unroll
        for (int j = 0; j < 64; j += 4) {
            s0 += z[j]; s1 += z[j + 1]; s2 += z[j + 2]; s3 += z[j + 3];
        }
        float tau = ((s0 + s1) + (s2 + s3) - 1.0f) * (1.0f / 64.0f);

        int cprev = 64;
#pragma unroll 1
        for (int it = 0; it < 64; ++it) {
            float t0 = 0.f, t1 = 0.f, t2 = 0.f, t3 = 0.f;
            int c0 = 0, c1 = 0, c2 = 0, c3 = 0;
#pragma unroll
            for (int j = 0; j < 64; j += 4) {
                if (z[j]     > tau) { t0 += z[j];     c0++; }
                if (z[j + 1] > tau) { t1 += z[j + 1]; c1++; }
                if (z[j + 2] > tau) { t2 += z[j + 2]; c2++; }
                if (z[j + 3] > tau) { t3 += z[j + 3]; c3++; }
            }
            int cc = (c0 + c1) + (c2 + c3);
            if (cc >= cprev) break;
            tau = ((t0 + t1) + (t2 + t3) - 1.0f) / (float)cc;
            cprev = cc;
        }

        float d0 = 0.f, d1 = 0.f, d2 = 0.f, d3 = 0.f;
#pragma unroll
        for (int j = 0; j < 64; j += 4) {
            d0 += fmaxf(z[j]     - tau, 0.0f) * z[j];
            d1 += fmaxf(z[j + 1] - tau, 0.0f) * z[j + 1];
            d2 += fmaxf(z[j + 2] - tau, 0.0f) * z[j + 2];
            d3 += fmaxf(z[j + 3] - tau, 0.0f) * z[j + 3];
        }
        float dot = (d0 + d1) + (d2 + d3);
        if (tid < 128) ((float*)(smc + SM_DOT))[tid] = dot;
        else           ((float*)(smc + SM_COL))[tid - 128] = dot;
    }
    __syncthreads();

    // ---- Weighted marginals: warp w = {cap0 rows, cap0 cols, cap1 rows, cap1 cols} ----
    if (tid < 128) {
        const int kind = wid & 1, cap = wid >> 1;
        const float* base =
            (const float*)(smc + (kind ? SM_COL : SM_DOT)) + cap * 64;
        const int len = kind ? (cap ? tlen1 : tlen0) : ilen;
        const float inv = 1.0f / (float)len;
        float a = (lane < len)      ? base[lane] * inv      : 0.0f;
        float b = (lane + 32 < len) ? base[lane + 32] * inv : 0.0f;
        float v = a + b;
#pragma unroll
        for (int o = 16; o > 0; o >>= 1) v += __shfl_xor_sync(0xffffffffu, v, o);
        if (lane == 0) ((float*)(smc + SM_RED))[wid] = v;
    }
    __syncthreads();

    if (tid == 0) {
        const float* red = (const float*)(smc + SM_RED);
        out[i * 128 + 2 * tp]     = 0.5f * (red[0] + red[1]);
        out[i * 128 + 2 * tp + 1] = 0.5f * (red[2] + red[3]);
    }
}

extern "C" void kernel_launch(void* const* d_in, const int* in_sizes, int n_in,
                              void* d_out, int out_size)
{
    // metadata order: img_cls, imgs, cap_cls, caps, img_lens, cap_lens
    const float* imgs = (const float*)d_in[1];
    const float* caps = (const float*)d_in[3];
    const int* img_lens = (const int*)d_in[4];
    const int* cap_lens = (const int*)d_in[5];
    float* out = (float*)d_out;

    static bool attr_done = false;
    if (!attr_done) {
        (void)cudaFuncSetAttribute(select_mma_kernel,
                                   cudaFuncAttributeMaxDynamicSharedMemorySize, SM_TOTAL);
        attr_done = true;
    }

    split_kernel<<<1024, 256>>>((const float4*)imgs, (const float4*)caps);
    dim3 grid(64, 128);   // (caption-pair, image)
    select_mma_kernel<<<grid, 256, SM_TOTAL>>>(img_lens, cap_lens, out);
}